// round 3
// baseline (speedup 1.0000x reference)
#include <cuda_runtime.h>
#include <cuda_bf16.h>

#define B_SZ   16
#define NUM_CN 25000
#define NUM_VN 50000
#define NUM_E  200000
#define D_EMB  16
#define D_HID  32
#define D_MSG  16

typedef unsigned long long ULL;

// ---- scratch (device globals; no allocation APIs allowed) ----
__device__ float g_hf_x[(size_t)B_SZ * NUM_CN * D_HID];   // [B][CN][32]
__device__ float g_hf_z[(size_t)B_SZ * NUM_CN * D_HID];
__device__ float g_m[(size_t)2 * B_SZ * NUM_VN * D_MSG];  // [pol][B][VN][16]
__device__ int      g_deg_x[NUM_VN],  g_deg_z[NUM_VN];
__device__ int      g_incl_x[NUM_VN], g_incl_z[NUM_VN];
__device__ int      g_bsum_x[64],     g_bsum_z[64];
__device__ int      g_offs_x[NUM_VN + 1], g_offs_z[NUM_VN + 1];
__device__ int      g_cur_x[NUM_VN],  g_cur_z[NUM_VN];
__device__ int      g_csr_x[NUM_E],   g_csr_z[NUM_E];
__device__ unsigned g_mask_x[NUM_CN], g_mask_z[NUM_CN];

// ---------------------------------------------------------------------------
// f32x2 packed-math helpers (sm_103a)
__device__ __forceinline__ ULL pk2(float x) {
    ULL d; asm("mov.b64 %0, {%1, %1};" : "=l"(d) : "f"(x)); return d;
}
__device__ __forceinline__ float2 up2(ULL a) {
    float lo, hi; asm("mov.b64 {%0, %1}, %2;" : "=f"(lo), "=f"(hi) : "l"(a));
    return make_float2(lo, hi);
}
__device__ __forceinline__ ULL f2fma(ULL a, ULL b, ULL c) {
    ULL d; asm("fma.rn.f32x2 %0, %1, %2, %3;" : "=l"(d) : "l"(a), "l"(b), "l"(c));
    return d;
}
__device__ __forceinline__ float4 mk4(ULL a, ULL b) {
    float2 p = up2(a), q = up2(b);
    return make_float4(p.x, p.y, q.x, q.y);
}

// ---------------------------------------------------------------------------
// CSR build: histogram -> scan -> fill
__global__ void __launch_bounds__(256) hist_kernel(
    const int* __restrict__ to_x, const int* __restrict__ to_z,
    int* __restrict__ deg_x, int* __restrict__ deg_z)
{
    int e = blockIdx.x * 256 + threadIdx.x;
    if (e >= NUM_E) return;
    atomicAdd(&deg_x[__ldg(to_x + e)], 1);
    atomicAdd(&deg_z[__ldg(to_z + e)], 1);
}

__global__ void __launch_bounds__(1024) scan1_kernel(
    const int* __restrict__ deg_x, const int* __restrict__ deg_z,
    int* __restrict__ incl_x, int* __restrict__ incl_z,
    int* __restrict__ bsum_x, int* __restrict__ bsum_z)
{
    const int* deg  = blockIdx.y == 0 ? deg_x  : deg_z;
    int*       incl = blockIdx.y == 0 ? incl_x : incl_z;
    int*       bsum = blockIdx.y == 0 ? bsum_x : bsum_z;
    __shared__ int s[1024];
    int t = threadIdx.x;
    int gid = blockIdx.x * 1024 + t;
    s[t] = (gid < NUM_VN) ? deg[gid] : 0;
    __syncthreads();
    #pragma unroll
    for (int off = 1; off < 1024; off <<= 1) {
        int x = (t >= off) ? s[t - off] : 0;
        __syncthreads();
        s[t] += x;
        __syncthreads();
    }
    if (gid < NUM_VN) incl[gid] = s[t];
    if (t == 1023) bsum[blockIdx.x] = s[t];
}

__global__ void __launch_bounds__(64) scan2_kernel(int* bsum_x, int* bsum_z, int nb)
{
    int* bs = blockIdx.x == 0 ? bsum_x : bsum_z;
    __shared__ int s[64];
    int t = threadIdx.x;
    s[t] = (t < nb) ? bs[t] : 0;
    __syncthreads();
    #pragma unroll
    for (int off = 1; off < 64; off <<= 1) {
        int x = (t >= off) ? s[t - off] : 0;
        __syncthreads();
        s[t] += x;
        __syncthreads();
    }
    if (t < nb) bs[t] = s[t];
}

__global__ void __launch_bounds__(1024) scan3_kernel(
    const int* __restrict__ incl_x, const int* __restrict__ incl_z,
    const int* __restrict__ bsum_x, const int* __restrict__ bsum_z,
    int* __restrict__ offs_x, int* __restrict__ offs_z)
{
    const int* incl = blockIdx.y == 0 ? incl_x : incl_z;
    const int* bsum = blockIdx.y == 0 ? bsum_x : bsum_z;
    int*       offs = blockIdx.y == 0 ? offs_x : offs_z;
    int gid = blockIdx.x * 1024 + threadIdx.x;
    if (gid < NUM_VN) {
        int add = (blockIdx.x > 0) ? bsum[blockIdx.x - 1] : 0;
        offs[gid + 1] = incl[gid] + add;
    }
    if (gid == 0) offs[0] = 0;
}

__global__ void __launch_bounds__(256) fill_kernel(
    const int* __restrict__ from_x, const int* __restrict__ to_x,
    const int* __restrict__ from_z, const int* __restrict__ to_z,
    const int* __restrict__ offs_x, const int* __restrict__ offs_z,
    int* __restrict__ cur_x, int* __restrict__ cur_z,
    int* __restrict__ csr_x, int* __restrict__ csr_z)
{
    int e = blockIdx.x * 256 + threadIdx.x;
    if (e >= NUM_E) return;
    {
        int v = __ldg(to_x + e);
        int p = atomicAdd(&cur_x[v], 1);
        csr_x[__ldg(offs_x + v) + p] = __ldg(from_x + e);
    }
    {
        int v = __ldg(to_z + e);
        int p = atomicAdd(&cur_z[v], 1);
        csr_z[__ldg(offs_z + v) + p] = __ldg(from_z + e);
    }
}

__global__ void __launch_bounds__(256) mask_kernel(
    const int* __restrict__ syn_x, const int* __restrict__ syn_z,
    unsigned* __restrict__ mask_x, unsigned* __restrict__ mask_z)
{
    const int* syn  = blockIdx.y == 0 ? syn_x  : syn_z;
    unsigned*  mask = blockIdx.y == 0 ? mask_x : mask_z;
    int f = blockIdx.x * 256 + threadIdx.x;
    if (f >= NUM_CN) return;
    unsigned m = 0;
    #pragma unroll
    for (int b = 0; b < B_SZ; b++)
        m |= (unsigned)(__ldg(syn + (size_t)b * NUM_CN + f) & 1) << b;
    mask[f] = m;
}

// ---------------------------------------------------------------------------
// CN partial: hf[r][j] = sum_{d<16} h[r][d] * W1[d][j], r = flat row over [B][CN]
// h [B][CN][16] and hf [B][CN][32] share the row index -> fully linear/coalesced
__global__ void __launch_bounds__(256) node_partial_kernel(
    const float* __restrict__ hx, const float* __restrict__ hz,
    const float* __restrict__ Wx1, const float* __restrict__ Wz1,
    float* __restrict__ ox, float* __restrict__ oz)
{
    const float* h  = blockIdx.y == 0 ? hx  : hz;
    const float* W1 = blockIdx.y == 0 ? Wx1 : Wz1;
    float*       o  = blockIdx.y == 0 ? ox  : oz;

    __shared__ ULL Ws[256];   // W1 rows 0..15 (16x32 packed pairs)
    int t = threadIdx.x;
    if (t < 256) Ws[t] = reinterpret_cast<const ULL*>(W1)[t];
    __syncthreads();

    int r = blockIdx.x * 256 + t;
    if (r >= B_SZ * NUM_CN) return;

    const float4* hp = reinterpret_cast<const float4*>(h + (size_t)r * D_EMB);
    float4 h0 = hp[0], h1 = hp[1], h2 = hp[2], h3 = hp[3];
    float hr[16] = {h0.x,h0.y,h0.z,h0.w, h1.x,h1.y,h1.z,h1.w,
                    h2.x,h2.y,h2.z,h2.w, h3.x,h3.y,h3.z,h3.w};

    ULL acc[16];
    #pragma unroll
    for (int q = 0; q < 16; q++) acc[q] = 0ull;
    #pragma unroll
    for (int d = 0; d < 16; d++) {
        ULL hd = pk2(hr[d]);
        #pragma unroll
        for (int q = 0; q < 16; q++) acc[q] = f2fma(hd, Ws[d*16 + q], acc[q]);
    }

    float4* op = reinterpret_cast<float4*>(o + (size_t)r * D_HID);
    #pragma unroll
    for (int q = 0; q < 8; q++) op[q] = mk4(acc[2*q], acc[2*q+1]);
}

// ---------------------------------------------------------------------------
// msg_kernel: per (pol, b, v) — inline h_to partial, walk CSR edges,
// msg = sum_e relu(hf[b][f] + hp) @ W2, store to m. No atomics.
__global__ void __launch_bounds__(128, 5) msg_kernel(
    const float* __restrict__ h_to,
    const float* __restrict__ hfx, const float* __restrict__ hfz,
    const int* __restrict__ offs_x, const int* __restrict__ csr_x,
    const int* __restrict__ offs_z, const int* __restrict__ csr_z,
    const unsigned* __restrict__ mask_x, const unsigned* __restrict__ mask_z,
    const float* __restrict__ Wx1, const float* __restrict__ Wz1,
    const float* __restrict__ Wx2, const float* __restrict__ Wz2,
    float* __restrict__ m)
{
    int pol = blockIdx.y;
    const float*    hf   = pol ? hfz   : hfx;
    const int*      offs = pol ? offs_z : offs_x;
    const int*      csr  = pol ? csr_z  : csr_x;
    const unsigned* msk  = pol ? mask_z : mask_x;
    const ULL* W1h = reinterpret_cast<const ULL*>((pol ? Wz1 : Wx1) + 16 * 32);
    const ULL* W2  = reinterpret_cast<const ULL*>(pol ? Wz2 : Wx2);

    __shared__ ULL sW1[256];   // W1 rows 16..31 (16x32)
    __shared__ ULL sW2[256];   // W2 (32x16)
    int t = threadIdx.x;
    for (int i = t; i < 256; i += 128) { sW1[i] = W1h[i]; sW2[i] = W2[i]; }
    __syncthreads();

    int idx = blockIdx.x * 128 + t;          // exact: B*VN = 800000 = 6250*128
    int b = idx / NUM_VN;
    int v = idx - b * NUM_VN;

    // hp = h_to row @ W1[16:32]  (16 -> 32)
    ULL hp[16];
    {
        const float4* ph = reinterpret_cast<const float4*>(h_to + (size_t)idx * D_EMB);
        float4 h0 = ph[0], h1 = ph[1], h2 = ph[2], h3 = ph[3];
        float htv[16] = {h0.x,h0.y,h0.z,h0.w, h1.x,h1.y,h1.z,h1.w,
                         h2.x,h2.y,h2.z,h2.w, h3.x,h3.y,h3.z,h3.w};
        #pragma unroll
        for (int q = 0; q < 16; q++) hp[q] = 0ull;
        #pragma unroll
        for (int d = 0; d < 16; d++) {
            ULL hd = pk2(htv[d]);
            #pragma unroll
            for (int q = 0; q < 16; q++) hp[q] = f2fma(hd, sW1[d*16 + q], hp[q]);
        }
    }

    ULL acc[8];
    #pragma unroll
    for (int q = 0; q < 8; q++) acc[q] = 0ull;

    int beg = __ldg(offs + v), end = __ldg(offs + v + 1);
    // prefetch one edge ahead
    int f_n = 0; unsigned mk_n = 0;
    if (beg < end) { f_n = __ldg(csr + beg); mk_n = __ldg(msk + f_n); }

    for (int e = beg; e < end; e++) {
        int f = f_n; unsigned mk = mk_n;
        if (e + 1 < end) { f_n = __ldg(csr + e + 1); mk_n = __ldg(msk + f_n); }
        if ((mk >> b) & 1u) {
            const float4* ap = reinterpret_cast<const float4*>(
                hf + ((size_t)b * NUM_CN + f) * D_HID);
            float hid[32];
            #pragma unroll
            for (int q = 0; q < 8; q++) {
                float4 a = ap[q];
                float2 p0 = up2(hp[2*q]), p1 = up2(hp[2*q+1]);
                hid[4*q+0] = fmaxf(a.x + p0.x, 0.f);
                hid[4*q+1] = fmaxf(a.y + p0.y, 0.f);
                hid[4*q+2] = fmaxf(a.z + p1.x, 0.f);
                hid[4*q+3] = fmaxf(a.w + p1.y, 0.f);
            }
            #pragma unroll
            for (int j = 0; j < 32; j++) {
                ULL hj = pk2(hid[j]);
                #pragma unroll
                for (int q = 0; q < 8; q++)
                    acc[q] = f2fma(hj, sW2[j*8 + q], acc[q]);
            }
        }
    }

    float4* op = reinterpret_cast<float4*>(
        m + ((size_t)pol * B_SZ * NUM_VN + idx) * D_MSG);
    #pragma unroll
    for (int q = 0; q < 4; q++) op[q] = mk4(acc[2*q], acc[2*q+1]);
}

// ---------------------------------------------------------------------------
// vn_kernel: out = relu([m_x|m_z|h_to] @ We1) @ We2 — fully linear streaming
__global__ void __launch_bounds__(256) vn_kernel(
    const float* __restrict__ m, const float* __restrict__ h_to,
    const float* __restrict__ We1, const float* __restrict__ We2,
    float* __restrict__ out)
{
    __shared__ ULL sW1[768];   // We1 48x32
    __shared__ ULL sW2[256];   // We2 32x16
    int t = threadIdx.x;
    for (int i = t; i < 768; i += 256) sW1[i] = reinterpret_cast<const ULL*>(We1)[i];
    if (t < 256) sW2[t] = reinterpret_cast<const ULL*>(We2)[t];
    __syncthreads();

    int idx = blockIdx.x * 256 + t;          // exact: 800000 = 3125*256
    const size_t BVN = (size_t)B_SZ * NUM_VN;

    float feat[48];
    {
        const float4* px = reinterpret_cast<const float4*>(m + (size_t)idx * D_MSG);
        const float4* pz = reinterpret_cast<const float4*>(m + (BVN + idx) * D_MSG);
        const float4* ph = reinterpret_cast<const float4*>(h_to + (size_t)idx * D_EMB);
        #pragma unroll
        for (int q = 0; q < 4; q++) {
            float4 a = px[q];
            feat[4*q+0]=a.x; feat[4*q+1]=a.y; feat[4*q+2]=a.z; feat[4*q+3]=a.w;
        }
        #pragma unroll
        for (int q = 0; q < 4; q++) {
            float4 a = pz[q];
            feat[16+4*q+0]=a.x; feat[16+4*q+1]=a.y; feat[16+4*q+2]=a.z; feat[16+4*q+3]=a.w;
        }
        #pragma unroll
        for (int q = 0; q < 4; q++) {
            float4 a = ph[q];
            feat[32+4*q+0]=a.x; feat[32+4*q+1]=a.y; feat[32+4*q+2]=a.z; feat[32+4*q+3]=a.w;
        }
    }

    ULL acc[16];
    #pragma unroll
    for (int q = 0; q < 16; q++) acc[q] = 0ull;
    #pragma unroll
    for (int d = 0; d < 48; d++) {
        ULL fd = pk2(feat[d]);
        #pragma unroll
        for (int q = 0; q < 16; q++) acc[q] = f2fma(fd, sW1[d*16 + q], acc[q]);
    }

    float hid[32];
    #pragma unroll
    for (int q = 0; q < 16; q++) {
        float2 p = up2(acc[q]);
        hid[2*q+0] = fmaxf(p.x, 0.f);
        hid[2*q+1] = fmaxf(p.y, 0.f);
    }

    ULL o[8];
    #pragma unroll
    for (int q = 0; q < 8; q++) o[q] = 0ull;
    #pragma unroll
    for (int j = 0; j < 32; j++) {
        ULL hj = pk2(hid[j]);
        #pragma unroll
        for (int q = 0; q < 8; q++) o[q] = f2fma(hj, sW2[j*8 + q], o[q]);
    }

    float4* op = reinterpret_cast<float4*>(out + (size_t)idx * D_EMB);
    #pragma unroll
    for (int q = 0; q < 4; q++) op[q] = mk4(o[2*q], o[2*q+1]);
}

// ---------------------------------------------------------------------------
extern "C" void kernel_launch(void* const* d_in, const int* in_sizes, int n_in,
                              void* d_out, int out_size) {
    const float* h_from_x   = (const float*)d_in[0];
    const float* h_from_z   = (const float*)d_in[1];
    const float* h_to       = (const float*)d_in[2];
    const int*   syndrome_x = (const int*)d_in[3];
    const int*   syndrome_z = (const int*)d_in[4];
    const int*   from_ind_x = (const int*)d_in[5];
    const int*   to_ind_x   = (const int*)d_in[6];
    const int*   from_ind_z = (const int*)d_in[7];
    const int*   to_ind_z   = (const int*)d_in[8];
    const float* Wx1        = (const float*)d_in[9];
    const float* Wx2        = (const float*)d_in[10];
    const float* Wz1        = (const float*)d_in[11];
    const float* Wz2        = (const float*)d_in[12];
    const float* We1        = (const float*)d_in[13];
    const float* We2        = (const float*)d_in[14];
    float* out = (float*)d_out;

    float *hf_x, *hf_z, *m;
    int *deg_x, *deg_z, *incl_x, *incl_z, *bsum_x, *bsum_z;
    int *offs_x, *offs_z, *cur_x, *cur_z, *csr_x, *csr_z;
    unsigned *mask_x, *mask_z;
    cudaGetSymbolAddress((void**)&hf_x, g_hf_x);
    cudaGetSymbolAddress((void**)&hf_z, g_hf_z);
    cudaGetSymbolAddress((void**)&m,    g_m);
    cudaGetSymbolAddress((void**)&deg_x, g_deg_x);
    cudaGetSymbolAddress((void**)&deg_z, g_deg_z);
    cudaGetSymbolAddress((void**)&incl_x, g_incl_x);
    cudaGetSymbolAddress((void**)&incl_z, g_incl_z);
    cudaGetSymbolAddress((void**)&bsum_x, g_bsum_x);
    cudaGetSymbolAddress((void**)&bsum_z, g_bsum_z);
    cudaGetSymbolAddress((void**)&offs_x, g_offs_x);
    cudaGetSymbolAddress((void**)&offs_z, g_offs_z);
    cudaGetSymbolAddress((void**)&cur_x, g_cur_x);
    cudaGetSymbolAddress((void**)&cur_z, g_cur_z);
    cudaGetSymbolAddress((void**)&csr_x, g_csr_x);
    cudaGetSymbolAddress((void**)&csr_z, g_csr_z);
    cudaGetSymbolAddress((void**)&mask_x, g_mask_x);
    cudaGetSymbolAddress((void**)&mask_z, g_mask_z);

    cudaMemsetAsync(deg_x, 0, NUM_VN * sizeof(int), 0);
    cudaMemsetAsync(deg_z, 0, NUM_VN * sizeof(int), 0);
    cudaMemsetAsync(cur_x, 0, NUM_VN * sizeof(int), 0);
    cudaMemsetAsync(cur_z, 0, NUM_VN * sizeof(int), 0);

    const int EB = (NUM_E + 255) / 256;
    const int SB = (NUM_VN + 1023) / 1024;     // 49

    hist_kernel<<<EB, 256>>>(to_ind_x, to_ind_z, deg_x, deg_z);
    scan1_kernel<<<dim3(SB, 2), 1024>>>(deg_x, deg_z, incl_x, incl_z, bsum_x, bsum_z);
    scan2_kernel<<<2, 64>>>(bsum_x, bsum_z, SB);
    scan3_kernel<<<dim3(SB, 2), 1024>>>(incl_x, incl_z, bsum_x, bsum_z, offs_x, offs_z);
    fill_kernel<<<EB, 256>>>(from_ind_x, to_ind_x, from_ind_z, to_ind_z,
                             offs_x, offs_z, cur_x, cur_z, csr_x, csr_z);
    mask_kernel<<<dim3((NUM_CN + 255) / 256, 2), 256>>>(syndrome_x, syndrome_z,
                                                        mask_x, mask_z);

    // CN-side hidden partials (both polarities, linear row mapping)
    node_partial_kernel<<<dim3((B_SZ * NUM_CN + 255) / 256, 2), 256>>>(
        h_from_x, h_from_z, Wx1, Wz1, hf_x, hf_z);

    // edge messages + per-VN reduction (registers, no atomics)
    msg_kernel<<<dim3((B_SZ * NUM_VN) / 128, 2), 128>>>(
        h_to, hf_x, hf_z,
        offs_x, csr_x, offs_z, csr_z, mask_x, mask_z,
        Wx1, Wz1, Wx2, Wz2, m);

    // vertex MLP
    vn_kernel<<<(B_SZ * NUM_VN) / 256, 256>>>(m, h_to, We1, We2, out);
}

// round 4
// speedup vs baseline: 1.2156x; 1.2156x over previous
#include <cuda_runtime.h>
#include <cuda_bf16.h>

#define B_SZ   16
#define NUM_CN 25000
#define NUM_VN 50000
#define NUM_E  200000
#define D_EMB  16
#define D_HID  32
#define D_MSG  16

typedef unsigned long long ULL;

// ---- scratch (device globals) ----
__device__ float g_hf_x[(size_t)NUM_CN * B_SZ * D_HID];   // [CN][B][32]
__device__ float g_hf_z[(size_t)NUM_CN * B_SZ * D_HID];
__device__ float g_m[(size_t)2 * NUM_VN * B_SZ * D_MSG];  // [pol][v*16+b][16]
__device__ int      g_deg_x[NUM_VN],  g_deg_z[NUM_VN];
__device__ int      g_offs_x[NUM_VN + 1], g_offs_z[NUM_VN + 1];
__device__ int      g_cur_x[NUM_VN],  g_cur_z[NUM_VN];
__device__ int      g_csr_x[NUM_E],   g_csr_z[NUM_E];
__device__ unsigned g_mask_x[NUM_CN], g_mask_z[NUM_CN];

// ---------------------------------------------------------------------------
// f32x2 packed helpers
__device__ __forceinline__ ULL pk2(float x) {
    ULL d; asm("mov.b64 %0, {%1, %1};" : "=l"(d) : "f"(x)); return d;
}
__device__ __forceinline__ ULL pkp(float x, float y) {
    ULL d; asm("mov.b64 %0, {%1, %2};" : "=l"(d) : "f"(x), "f"(y)); return d;
}
__device__ __forceinline__ float2 up2(ULL a) {
    float lo, hi; asm("mov.b64 {%0, %1}, %2;" : "=f"(lo), "=f"(hi) : "l"(a));
    return make_float2(lo, hi);
}
__device__ __forceinline__ ULL f2fma(ULL a, ULL b, ULL c) {
    ULL d; asm("fma.rn.f32x2 %0, %1, %2, %3;" : "=l"(d) : "l"(a), "l"(b), "l"(c));
    return d;
}
__device__ __forceinline__ ULL add2(ULL a, ULL b) {
    ULL d; asm("add.rn.f32x2 %0, %1, %2;" : "=l"(d) : "l"(a), "l"(b));
    return d;
}
__device__ __forceinline__ float4 mk4(ULL a, ULL b) {
    float2 p = up2(a), q = up2(b);
    return make_float4(p.x, p.y, q.x, q.y);
}

// ---------------------------------------------------------------------------
// kernel 0: histogram + syndrome bitmask pack
__global__ void __launch_bounds__(256) prep_kernel(
    const int* __restrict__ to_x, const int* __restrict__ to_z,
    const int* __restrict__ syn_x, const int* __restrict__ syn_z,
    int* __restrict__ deg_x, int* __restrict__ deg_z,
    unsigned* __restrict__ mask_x, unsigned* __restrict__ mask_z)
{
    int i = blockIdx.x * 256 + threadIdx.x;
    if (i < NUM_E) {
        atomicAdd(&deg_x[__ldg(to_x + i)], 1);
        atomicAdd(&deg_z[__ldg(to_z + i)], 1);
    }
    if (i < NUM_CN) {
        unsigned mx = 0, mz = 0;
        #pragma unroll
        for (int b = 0; b < B_SZ; b++) {
            mx |= (unsigned)(__ldg(syn_x + (size_t)b * NUM_CN + i) & 1) << b;
            mz |= (unsigned)(__ldg(syn_z + (size_t)b * NUM_CN + i) & 1) << b;
        }
        mask_x[i] = mx;
        mask_z[i] = mz;
    }
}

// ---------------------------------------------------------------------------
// single-block exclusive scan over one polarity's degree array
__device__ void block_scan_pol(const int* __restrict__ deg, int* __restrict__ offs)
{
    __shared__ int warp_tot[8];
    __shared__ int s_base;
    int t = threadIdx.x;
    if (t == 0) s_base = 0;
    __syncthreads();
    int lane = t & 31, w = t >> 5;
    for (int c = 0; c < NUM_VN; c += 256) {
        int gid = c + t;
        int val = (gid < NUM_VN) ? deg[gid] : 0;
        int x = val;
        #pragma unroll
        for (int o = 1; o < 32; o <<= 1) {
            int y = __shfl_up_sync(0xffffffffu, x, o);
            if (lane >= o) x += y;
        }
        if (lane == 31) warp_tot[w] = x;
        __syncthreads();
        int woff = 0;
        #pragma unroll
        for (int ww = 0; ww < 8; ww++) woff += (ww < w) ? warp_tot[ww] : 0;
        int incl = x + woff;
        int base = s_base;
        __syncthreads();
        if (t == 255) s_base = base + incl;
        if (gid < NUM_VN) offs[gid + 1] = base + incl;
        __syncthreads();
    }
    if (t == 0) offs[0] = 0;
}

// kernel 1: node partials (y=0,1) + CSR offset scan (y=2, block x=0 only)
__global__ void __launch_bounds__(256) scan_np_kernel(
    const float* __restrict__ hx, const float* __restrict__ hz,
    const float* __restrict__ Wx1, const float* __restrict__ Wz1,
    float* __restrict__ ox, float* __restrict__ oz,
    const int* __restrict__ deg_x, const int* __restrict__ deg_z,
    int* __restrict__ offs_x, int* __restrict__ offs_z)
{
    if (blockIdx.y == 2) {
        if (blockIdx.x != 0) return;
        block_scan_pol(deg_x, offs_x);
        __syncthreads();
        block_scan_pol(deg_z, offs_z);
        return;
    }
    const float* h  = blockIdx.y == 0 ? hx  : hz;
    const float* W1 = blockIdx.y == 0 ? Wx1 : Wz1;
    float*       o  = blockIdx.y == 0 ? ox  : oz;

    __shared__ float4 Ws[128];   // W1 rows 0..15 : 16x32 floats
    int t = threadIdx.x;
    if (t < 128) Ws[t] = reinterpret_cast<const float4*>(W1)[t];
    __syncthreads();

    int idx = blockIdx.x * 256 + t;           // idx = n*16 + b
    if (idx >= NUM_CN * B_SZ) return;
    int n = idx >> 4, b = idx & 15;

    const float4* hp = reinterpret_cast<const float4*>(h + ((size_t)b * NUM_CN + n) * D_EMB);
    float4 h0 = hp[0], h1 = hp[1], h2 = hp[2], h3 = hp[3];
    float hr[16] = {h0.x,h0.y,h0.z,h0.w, h1.x,h1.y,h1.z,h1.w,
                    h2.x,h2.y,h2.z,h2.w, h3.x,h3.y,h3.z,h3.w};

    ULL acc[16];
    #pragma unroll
    for (int q = 0; q < 16; q++) acc[q] = 0ull;
    #pragma unroll
    for (int d = 0; d < 16; d++) {
        ULL hd = pk2(hr[d]);
        #pragma unroll
        for (int k = 0; k < 8; k++) {
            float4 w = Ws[d*8 + k];
            acc[2*k+0] = f2fma(hd, pkp(w.x, w.y), acc[2*k+0]);
            acc[2*k+1] = f2fma(hd, pkp(w.z, w.w), acc[2*k+1]);
        }
    }

    float4* op = reinterpret_cast<float4*>(o + (size_t)idx * D_HID);
    #pragma unroll
    for (int q = 0; q < 8; q++) op[q] = mk4(acc[2*q], acc[2*q+1]);
}

// ---------------------------------------------------------------------------
// kernel 2: fill CSR payload
__global__ void __launch_bounds__(256) fill_kernel(
    const int* __restrict__ from_x, const int* __restrict__ to_x,
    const int* __restrict__ from_z, const int* __restrict__ to_z,
    const int* __restrict__ offs_x, const int* __restrict__ offs_z,
    int* __restrict__ cur_x, int* __restrict__ cur_z,
    int* __restrict__ csr_x, int* __restrict__ csr_z)
{
    int e = blockIdx.x * 256 + threadIdx.x;
    if (e >= NUM_E) return;
    {
        int v = __ldg(to_x + e);
        int p = atomicAdd(&cur_x[v], 1);
        csr_x[__ldg(offs_x + v) + p] = __ldg(from_x + e);
    }
    {
        int v = __ldg(to_z + e);
        int p = atomicAdd(&cur_z[v], 1);
        csr_z[__ldg(offs_z + v) + p] = __ldg(from_z + e);
    }
}

// ---------------------------------------------------------------------------
// kernel 3 (profiled): per (pol, v, b):
//   hp = h_to[v,b] @ W1[16:32]           (16->32)
//   s  = sum_{e in edges(v), syn} relu(hf[f_e,b] + hp)    (32-dim, NO per-edge GEMM)
//   msg = s @ W2                          (32->16, once)
__global__ void __launch_bounds__(128, 4) msg_kernel(
    const float* __restrict__ h_to,
    const float* __restrict__ hfx, const float* __restrict__ hfz,
    const int* __restrict__ offs_x, const int* __restrict__ csr_x,
    const int* __restrict__ offs_z, const int* __restrict__ csr_z,
    const unsigned* __restrict__ mask_x, const unsigned* __restrict__ mask_z,
    const float* __restrict__ Wx1, const float* __restrict__ Wz1,
    const float* __restrict__ Wx2, const float* __restrict__ Wz2,
    float* __restrict__ m)
{
    int pol = blockIdx.y;
    const float*    hf   = pol ? hfz    : hfx;
    const int*      offs = pol ? offs_z : offs_x;
    const int*      csr  = pol ? csr_z  : csr_x;
    const unsigned* msk  = pol ? mask_z : mask_x;

    __shared__ float4 sW1[128];   // W1 rows 16..31 : 16x32
    __shared__ float4 sW2[128];   // W2 : 32x16
    {
        const float4* w1 = reinterpret_cast<const float4*>((pol ? Wz1 : Wx1) + 16 * 32);
        const float4* w2 = reinterpret_cast<const float4*>(pol ? Wz2 : Wx2);
        int t = threadIdx.x;
        if (t < 128) sW1[t] = w1[t];
        else ;
        // second array loaded by same 128 threads
        if (t < 128) sW2[t] = w2[t];
    }
    __syncthreads();

    int idx = blockIdx.x * 128 + threadIdx.x;   // idx = v*16 + b  (800000 total)
    int v = idx >> 4;
    int b = idx & 15;

    // hp = h_to[b][v] @ W1half
    ULL hp[16];
    {
        const float4* ph = reinterpret_cast<const float4*>(
            h_to + ((size_t)b * NUM_VN + v) * D_EMB);
        float4 h0 = ph[0], h1 = ph[1], h2 = ph[2], h3 = ph[3];
        float htv[16] = {h0.x,h0.y,h0.z,h0.w, h1.x,h1.y,h1.z,h1.w,
                         h2.x,h2.y,h2.z,h2.w, h3.x,h3.y,h3.z,h3.w};
        #pragma unroll
        for (int q = 0; q < 16; q++) hp[q] = 0ull;
        #pragma unroll
        for (int d = 0; d < 16; d++) {
            ULL hd = pk2(htv[d]);
            #pragma unroll
            for (int k = 0; k < 8; k++) {
                float4 w = sW1[d*8 + k];
                hp[2*k+0] = f2fma(hd, pkp(w.x, w.y), hp[2*k+0]);
                hp[2*k+1] = f2fma(hd, pkp(w.z, w.w), hp[2*k+1]);
            }
        }
    }

    // s accumulator (32-dim as 16 packed pairs)
    ULL s[16];
    #pragma unroll
    for (int q = 0; q < 16; q++) s[q] = 0ull;

    int beg = __ldg(offs + v), end = __ldg(offs + v + 1);
    int deg = end - beg;
    int degO = __shfl_xor_sync(0xffffffffu, deg, 16);
    int md = max(deg, degO);           // uniform across warp -> no loop divergence

    int f_n = 0; unsigned mk_n = 0;
    if (0 < deg) { f_n = __ldg(csr + beg); mk_n = __ldg(msk + f_n); }

    for (int i = 0; i < md; i++) {
        int f = f_n; unsigned mk = mk_n;
        bool act = (i < deg);
        if (i + 1 < deg) { f_n = __ldg(csr + beg + i + 1); mk_n = __ldg(msk + f_n); }
        if (act && ((mk >> b) & 1u)) {
            const float4* ap = reinterpret_cast<const float4*>(
                hf + ((size_t)f * B_SZ + b) * D_HID);
            #pragma unroll
            for (int k = 0; k < 8; k++) {
                float4 a = ap[k];
                ULL t0 = add2(pkp(a.x, a.y), hp[2*k+0]);
                ULL t1 = add2(pkp(a.z, a.w), hp[2*k+1]);
                float2 p0 = up2(t0), p1 = up2(t1);
                // relu on alu pipe (FMNMX), repack free
                float r0 = fmaxf(p0.x, 0.f), r1 = fmaxf(p0.y, 0.f);
                float r2 = fmaxf(p1.x, 0.f), r3 = fmaxf(p1.y, 0.f);
                s[2*k+0] = add2(s[2*k+0], pkp(r0, r1));
                s[2*k+1] = add2(s[2*k+1], pkp(r2, r3));
            }
        }
    }

    // msg = s @ W2   (32 -> 16)
    float sv[32];
    #pragma unroll
    for (int q = 0; q < 16; q++) {
        float2 p = up2(s[q]);
        sv[2*q+0] = p.x; sv[2*q+1] = p.y;
    }
    ULL acc[8];
    #pragma unroll
    for (int q = 0; q < 8; q++) acc[q] = 0ull;
    #pragma unroll
    for (int j = 0; j < 32; j++) {
        ULL hj = pk2(sv[j]);
        #pragma unroll
        for (int k = 0; k < 4; k++) {
            float4 w = sW2[j*4 + k];
            acc[2*k+0] = f2fma(hj, pkp(w.x, w.y), acc[2*k+0]);
            acc[2*k+1] = f2fma(hj, pkp(w.z, w.w), acc[2*k+1]);
        }
    }

    float4* op = reinterpret_cast<float4*>(
        m + ((size_t)pol * NUM_VN * B_SZ + idx) * D_MSG);
    #pragma unroll
    for (int q = 0; q < 4; q++) op[q] = mk4(acc[2*q], acc[2*q+1]);
}

// ---------------------------------------------------------------------------
// kernel 4: out = relu([m_x|m_z|h_to] @ We1) @ We2
__global__ void __launch_bounds__(256, 2) vn_kernel(
    const float* __restrict__ m, const float* __restrict__ h_to,
    const float* __restrict__ We1, const float* __restrict__ We2,
    float* __restrict__ out)
{
    __shared__ float4 sW1[384];   // We1 48x32
    __shared__ float4 sW2[128];   // We2 32x16
    int t = threadIdx.x;
    for (int i = t; i < 384; i += 256) sW1[i] = reinterpret_cast<const float4*>(We1)[i];
    if (t < 128) sW2[t] = reinterpret_cast<const float4*>(We2)[t];
    __syncthreads();

    int idx = blockIdx.x * 256 + t;   // idx = v*16 + b
    int v = idx >> 4;
    int b = idx & 15;
    const size_t BVN = (size_t)NUM_VN * B_SZ;

    float feat[48];
    {
        const float4* px = reinterpret_cast<const float4*>(m + (size_t)idx * D_MSG);
        const float4* pz = reinterpret_cast<const float4*>(m + (BVN + idx) * D_MSG);
        const float4* ph = reinterpret_cast<const float4*>(
            h_to + ((size_t)b * NUM_VN + v) * D_EMB);
        #pragma unroll
        for (int q = 0; q < 4; q++) {
            float4 a = px[q];
            feat[4*q+0]=a.x; feat[4*q+1]=a.y; feat[4*q+2]=a.z; feat[4*q+3]=a.w;
        }
        #pragma unroll
        for (int q = 0; q < 4; q++) {
            float4 a = pz[q];
            feat[16+4*q+0]=a.x; feat[16+4*q+1]=a.y; feat[16+4*q+2]=a.z; feat[16+4*q+3]=a.w;
        }
        #pragma unroll
        for (int q = 0; q < 4; q++) {
            float4 a = ph[q];
            feat[32+4*q+0]=a.x; feat[32+4*q+1]=a.y; feat[32+4*q+2]=a.z; feat[32+4*q+3]=a.w;
        }
    }

    ULL acc[16];
    #pragma unroll
    for (int q = 0; q < 16; q++) acc[q] = 0ull;
    #pragma unroll
    for (int d = 0; d < 48; d++) {
        ULL fd = pk2(feat[d]);
        #pragma unroll
        for (int k = 0; k < 8; k++) {
            float4 w = sW1[d*8 + k];
            acc[2*k+0] = f2fma(fd, pkp(w.x, w.y), acc[2*k+0]);
            acc[2*k+1] = f2fma(fd, pkp(w.z, w.w), acc[2*k+1]);
        }
    }

    float hid[32];
    #pragma unroll
    for (int q = 0; q < 16; q++) {
        float2 p = up2(acc[q]);
        hid[2*q+0] = fmaxf(p.x, 0.f);
        hid[2*q+1] = fmaxf(p.y, 0.f);
    }

    ULL o[8];
    #pragma unroll
    for (int q = 0; q < 8; q++) o[q] = 0ull;
    #pragma unroll
    for (int j = 0; j < 32; j++) {
        ULL hj = pk2(hid[j]);
        #pragma unroll
        for (int k = 0; k < 4; k++) {
            float4 w = sW2[j*4 + k];
            o[2*k+0] = f2fma(hj, pkp(w.x, w.y), o[2*k+0]);
            o[2*k+1] = f2fma(hj, pkp(w.z, w.w), o[2*k+1]);
        }
    }

    float4* op = reinterpret_cast<float4*>(out + ((size_t)b * NUM_VN + v) * D_EMB);
    #pragma unroll
    for (int q = 0; q < 4; q++) op[q] = mk4(o[2*q], o[2*q+1]);
}

// ---------------------------------------------------------------------------
extern "C" void kernel_launch(void* const* d_in, const int* in_sizes, int n_in,
                              void* d_out, int out_size) {
    const float* h_from_x   = (const float*)d_in[0];
    const float* h_from_z   = (const float*)d_in[1];
    const float* h_to       = (const float*)d_in[2];
    const int*   syndrome_x = (const int*)d_in[3];
    const int*   syndrome_z = (const int*)d_in[4];
    const int*   from_ind_x = (const int*)d_in[5];
    const int*   to_ind_x   = (const int*)d_in[6];
    const int*   from_ind_z = (const int*)d_in[7];
    const int*   to_ind_z   = (const int*)d_in[8];
    const float* Wx1        = (const float*)d_in[9];
    const float* Wx2        = (const float*)d_in[10];
    const float* Wz1        = (const float*)d_in[11];
    const float* Wz2        = (const float*)d_in[12];
    const float* We1        = (const float*)d_in[13];
    const float* We2        = (const float*)d_in[14];
    float* out = (float*)d_out;

    float *hf_x, *hf_z, *m;
    int *deg_x, *deg_z, *offs_x, *offs_z, *cur_x, *cur_z, *csr_x, *csr_z;
    unsigned *mask_x, *mask_z;
    cudaGetSymbolAddress((void**)&hf_x, g_hf_x);
    cudaGetSymbolAddress((void**)&hf_z, g_hf_z);
    cudaGetSymbolAddress((void**)&m,    g_m);
    cudaGetSymbolAddress((void**)&deg_x, g_deg_x);
    cudaGetSymbolAddress((void**)&deg_z, g_deg_z);
    cudaGetSymbolAddress((void**)&offs_x, g_offs_x);
    cudaGetSymbolAddress((void**)&offs_z, g_offs_z);
    cudaGetSymbolAddress((void**)&cur_x, g_cur_x);
    cudaGetSymbolAddress((void**)&cur_z, g_cur_z);
    cudaGetSymbolAddress((void**)&csr_x, g_csr_x);
    cudaGetSymbolAddress((void**)&csr_z, g_csr_z);
    cudaGetSymbolAddress((void**)&mask_x, g_mask_x);
    cudaGetSymbolAddress((void**)&mask_z, g_mask_z);

    cudaMemsetAsync(deg_x, 0, NUM_VN * sizeof(int), 0);
    cudaMemsetAsync(deg_z, 0, NUM_VN * sizeof(int), 0);
    cudaMemsetAsync(cur_x, 0, NUM_VN * sizeof(int), 0);
    cudaMemsetAsync(cur_z, 0, NUM_VN * sizeof(int), 0);

    // kernel 0: histogram + masks
    prep_kernel<<<(NUM_E + 255) / 256, 256>>>(
        to_ind_x, to_ind_z, syndrome_x, syndrome_z,
        deg_x, deg_z, mask_x, mask_z);

    // kernel 1: node partials (y=0,1) + offset scan (y=2)
    scan_np_kernel<<<dim3((NUM_CN * B_SZ + 255) / 256, 3), 256>>>(
        h_from_x, h_from_z, Wx1, Wz1, hf_x, hf_z,
        deg_x, deg_z, offs_x, offs_z);

    // kernel 2: CSR fill
    fill_kernel<<<(NUM_E + 255) / 256, 256>>>(
        from_ind_x, to_ind_x, from_ind_z, to_ind_z,
        offs_x, offs_z, cur_x, cur_z, csr_x, csr_z);

    // kernel 3: messages (sum-then-project) — lands at ncu capture slot
    msg_kernel<<<dim3((NUM_VN * B_SZ) / 128, 2), 128>>>(
        h_to, hf_x, hf_z,
        offs_x, csr_x, offs_z, csr_z, mask_x, mask_z,
        Wx1, Wz1, Wx2, Wz2, m);

    // kernel 4: vertex MLP
    vn_kernel<<<(NUM_VN * B_SZ) / 256, 256>>>(m, h_to, We1, We2, out);
}

// round 5
// speedup vs baseline: 1.3896x; 1.1432x over previous
#include <cuda_runtime.h>
#include <cuda_bf16.h>

#define B_SZ   16
#define NUM_CN 25000
#define NUM_VN 50000
#define NUM_E  200000
#define D_EMB  16
#define D_HID  32
#define D_MSG  16

typedef unsigned long long ULL;

// ---- scratch (device globals) ----
__device__ float g_hf_x[(size_t)NUM_CN * B_SZ * D_HID];   // [CN][B][32]
__device__ float g_hf_z[(size_t)NUM_CN * B_SZ * D_HID];
__device__ float g_m[(size_t)2 * NUM_VN * B_SZ * D_MSG];  // [pol][v*16+b][16]
__device__ int      g_cnt[4 * NUM_VN];                    // deg_x|deg_z|cur_x|cur_z
__device__ int      g_incl_x[NUM_VN], g_incl_z[NUM_VN];
__device__ int      g_bsum_x[64],     g_bsum_z[64];
__device__ int      g_offs_x[NUM_VN + 1], g_offs_z[NUM_VN + 1];
__device__ int      g_csr_x[NUM_E],   g_csr_z[NUM_E];
__device__ unsigned g_mask_x[NUM_CN], g_mask_z[NUM_CN];

// ---------------------------------------------------------------------------
// f32x2 packed helpers
__device__ __forceinline__ ULL pk2(float x) {
    ULL d; asm("mov.b64 %0, {%1, %1};" : "=l"(d) : "f"(x)); return d;
}
__device__ __forceinline__ ULL pkp(float x, float y) {
    ULL d; asm("mov.b64 %0, {%1, %2};" : "=l"(d) : "f"(x), "f"(y)); return d;
}
__device__ __forceinline__ float2 up2(ULL a) {
    float lo, hi; asm("mov.b64 {%0, %1}, %2;" : "=f"(lo), "=f"(hi) : "l"(a));
    return make_float2(lo, hi);
}
__device__ __forceinline__ ULL f2fma(ULL a, ULL b, ULL c) {
    ULL d; asm("fma.rn.f32x2 %0, %1, %2, %3;" : "=l"(d) : "l"(a), "l"(b), "l"(c));
    return d;
}
__device__ __forceinline__ ULL add2(ULL a, ULL b) {
    ULL d; asm("add.rn.f32x2 %0, %1, %2;" : "=l"(d) : "l"(a), "l"(b));
    return d;
}
__device__ __forceinline__ float4 mk4(ULL a, ULL b) {
    float2 p = up2(a), q = up2(b);
    return make_float4(p.x, p.y, q.x, q.y);
}

// ---------------------------------------------------------------------------
// kernel 0: degree histogram + syndrome bitmask pack
__global__ void __launch_bounds__(256) prep_kernel(
    const int* __restrict__ to_x, const int* __restrict__ to_z,
    const int* __restrict__ syn_x, const int* __restrict__ syn_z,
    int* __restrict__ deg_x, int* __restrict__ deg_z,
    unsigned* __restrict__ mask_x, unsigned* __restrict__ mask_z)
{
    int i = blockIdx.x * 256 + threadIdx.x;
    if (i < NUM_E) {
        atomicAdd(&deg_x[__ldg(to_x + i)], 1);
        atomicAdd(&deg_z[__ldg(to_z + i)], 1);
    }
    if (i < NUM_CN) {
        unsigned mx = 0, mz = 0;
        #pragma unroll
        for (int b = 0; b < B_SZ; b++) {
            mx |= (unsigned)(__ldg(syn_x + (size_t)b * NUM_CN + i) & 1) << b;
            mz |= (unsigned)(__ldg(syn_z + (size_t)b * NUM_CN + i) & 1) << b;
        }
        mask_x[i] = mx;
        mask_z[i] = mz;
    }
}

// ---------------------------------------------------------------------------
// parallel scan (3 kernels), polarity via blockIdx.y
__global__ void __launch_bounds__(1024) scan1_kernel(
    const int* __restrict__ deg_x, const int* __restrict__ deg_z,
    int* __restrict__ incl_x, int* __restrict__ incl_z,
    int* __restrict__ bsum_x, int* __restrict__ bsum_z)
{
    const int* deg  = blockIdx.y == 0 ? deg_x  : deg_z;
    int*       incl = blockIdx.y == 0 ? incl_x : incl_z;
    int*       bsum = blockIdx.y == 0 ? bsum_x : bsum_z;
    __shared__ int s[1024];
    int t = threadIdx.x;
    int gid = blockIdx.x * 1024 + t;
    s[t] = (gid < NUM_VN) ? deg[gid] : 0;
    __syncthreads();
    #pragma unroll
    for (int off = 1; off < 1024; off <<= 1) {
        int x = (t >= off) ? s[t - off] : 0;
        __syncthreads();
        s[t] += x;
        __syncthreads();
    }
    if (gid < NUM_VN) incl[gid] = s[t];
    if (t == 1023) bsum[blockIdx.x] = s[t];
}

__global__ void __launch_bounds__(64) scan2_kernel(int* bsum_x, int* bsum_z, int nb)
{
    int* bs = blockIdx.x == 0 ? bsum_x : bsum_z;
    __shared__ int s[64];
    int t = threadIdx.x;
    s[t] = (t < nb) ? bs[t] : 0;
    __syncthreads();
    #pragma unroll
    for (int off = 1; off < 64; off <<= 1) {
        int x = (t >= off) ? s[t - off] : 0;
        __syncthreads();
        s[t] += x;
        __syncthreads();
    }
    if (t < nb) bs[t] = s[t];
}

__global__ void __launch_bounds__(1024) scan3_kernel(
    const int* __restrict__ incl_x, const int* __restrict__ incl_z,
    const int* __restrict__ bsum_x, const int* __restrict__ bsum_z,
    int* __restrict__ offs_x, int* __restrict__ offs_z)
{
    const int* incl = blockIdx.y == 0 ? incl_x : incl_z;
    const int* bsum = blockIdx.y == 0 ? bsum_x : bsum_z;
    int*       offs = blockIdx.y == 0 ? offs_x : offs_z;
    int gid = blockIdx.x * 1024 + threadIdx.x;
    if (gid < NUM_VN) {
        int add = (blockIdx.x > 0) ? bsum[blockIdx.x - 1] : 0;
        offs[gid + 1] = incl[gid] + add;
    }
    if (gid == 0) offs[0] = 0;
}

// ---------------------------------------------------------------------------
// fill CSR payload
__global__ void __launch_bounds__(256) fill_kernel(
    const int* __restrict__ from_x, const int* __restrict__ to_x,
    const int* __restrict__ from_z, const int* __restrict__ to_z,
    const int* __restrict__ offs_x, const int* __restrict__ offs_z,
    int* __restrict__ cur_x, int* __restrict__ cur_z,
    int* __restrict__ csr_x, int* __restrict__ csr_z)
{
    int e = blockIdx.x * 256 + threadIdx.x;
    if (e >= NUM_E) return;
    {
        int v = __ldg(to_x + e);
        int p = atomicAdd(&cur_x[v], 1);
        csr_x[__ldg(offs_x + v) + p] = __ldg(from_x + e);
    }
    {
        int v = __ldg(to_z + e);
        int p = atomicAdd(&cur_z[v], 1);
        csr_z[__ldg(offs_z + v) + p] = __ldg(from_z + e);
    }
}

// ---------------------------------------------------------------------------
// node partials, cooperative layout:
// warp = one n x 4 consecutive b; lane = b_local*8 + chunk; lane owns 4 outputs.
// hf[(n*16+b)*32 + chunk*4 .. +4] = sum_d h[b][n][d] * W1[d][chunk*4 ..]
__global__ void __launch_bounds__(256) np_kernel(
    const float* __restrict__ hx, const float* __restrict__ hz,
    const float* __restrict__ Wx1, const float* __restrict__ Wz1,
    float* __restrict__ ox, float* __restrict__ oz)
{
    const float* h  = blockIdx.y == 0 ? hx  : hz;
    const float* W1 = blockIdx.y == 0 ? Wx1 : Wz1;
    float*       o  = blockIdx.y == 0 ? ox  : oz;

    __shared__ float4 sW1[128];   // W1 rows 0..15 (16x32)
    int t = threadIdx.x;
    if (t < 128) sW1[t] = reinterpret_cast<const float4*>(W1)[t];
    __syncthreads();

    int wid = t >> 5;
    int unit = blockIdx.x * 8 + wid;          // n*4 + bgroup, < 100000
    int n = unit >> 2;
    int b = ((unit & 3) << 2) | ((t >> 3) & 3);
    int chunk = t & 7;

    // load h[b][n][0..16]
    const float4* ph = reinterpret_cast<const float4*>(h + ((size_t)b * NUM_CN + n) * D_EMB);
    float4 h0 = ph[0], h1 = ph[1], h2 = ph[2], h3 = ph[3];
    float hr[16] = {h0.x,h0.y,h0.z,h0.w, h1.x,h1.y,h1.z,h1.w,
                    h2.x,h2.y,h2.z,h2.w, h3.x,h3.y,h3.z,h3.w};

    ULL a0 = 0ull, a1 = 0ull;
    #pragma unroll
    for (int d = 0; d < 16; d++) {
        float4 w = sW1[d*8 + chunk];
        ULL hd = pk2(hr[d]);
        a0 = f2fma(hd, pkp(w.x, w.y), a0);
        a1 = f2fma(hd, pkp(w.z, w.w), a1);
    }

    reinterpret_cast<float4*>(o)[((size_t)n * B_SZ + b) * 8 + chunk] = mk4(a0, a1);
}

// ---------------------------------------------------------------------------
// msg kernel, cooperative layout:
// warp = one v x 4 consecutive b; lane = b_local*8 + chunk owns hidden dims chunk*4..+4.
//   hp = h_to[v,b] @ W1[16:32]  (lane: 4 dims)
//   s  = sum_{edges(v), syn bit b} relu(hf[f,b] + hp)
//   msg= s @ W2 via width-8 shfl broadcast; lane stores out dims 2*chunk..+2
__global__ void __launch_bounds__(256) msg_kernel(
    const float* __restrict__ h_to,
    const float* __restrict__ hfx, const float* __restrict__ hfz,
    const int* __restrict__ offs_x, const int* __restrict__ csr_x,
    const int* __restrict__ offs_z, const int* __restrict__ csr_z,
    const unsigned* __restrict__ mask_x, const unsigned* __restrict__ mask_z,
    const float* __restrict__ Wx1, const float* __restrict__ Wz1,
    const float* __restrict__ Wx2, const float* __restrict__ Wz2,
    float* __restrict__ m)
{
    int pol = blockIdx.y;
    const float*    hf   = pol ? hfz    : hfx;
    const int*      offs = pol ? offs_z : offs_x;
    const int*      csr  = pol ? csr_z  : csr_x;
    const unsigned* msk  = pol ? mask_z : mask_x;

    __shared__ float4 sW1[128];   // W1 rows 16..31 (16x32)
    __shared__ float  sW2[512];   // W2 (32x16)
    {
        const float4* w1 = reinterpret_cast<const float4*>((pol ? Wz1 : Wx1) + 16 * 32);
        const float4* w2 = reinterpret_cast<const float4*>(pol ? Wz2 : Wx2);
        int t = threadIdx.x;
        if (t < 128) {
            sW1[t] = w1[t];
            reinterpret_cast<float4*>(sW2)[t] = w2[t];
        }
    }
    __syncthreads();

    int t = threadIdx.x;
    int wid = t >> 5;
    int unit = blockIdx.x * 8 + wid;          // v*4 + bgroup, < 200000
    int v = unit >> 2;
    int b = ((unit & 3) << 2) | ((t >> 3) & 3);
    int chunk = t & 7;

    // hp: lane's 4 hidden dims of h_to-partial
    ULL hp0 = 0ull, hp1 = 0ull;
    {
        const float4* ph = reinterpret_cast<const float4*>(
            h_to + ((size_t)b * NUM_VN + v) * D_EMB);
        float4 h0 = ph[0], h1 = ph[1], h2 = ph[2], h3 = ph[3];
        float hr[16] = {h0.x,h0.y,h0.z,h0.w, h1.x,h1.y,h1.z,h1.w,
                        h2.x,h2.y,h2.z,h2.w, h3.x,h3.y,h3.z,h3.w};
        #pragma unroll
        for (int d = 0; d < 16; d++) {
            float4 w = sW1[d*8 + chunk];
            ULL hd = pk2(hr[d]);
            hp0 = f2fma(hd, pkp(w.x, w.y), hp0);
            hp1 = f2fma(hd, pkp(w.z, w.w), hp1);
        }
    }
    float2 hpa = up2(hp0), hpb = up2(hp1);

    // edge accumulation: lane's 4 hidden dims
    float s0 = 0.f, s1 = 0.f, s2 = 0.f, s3 = 0.f;
    int beg = __ldg(offs + v), end = __ldg(offs + v + 1);
    const float4* hf4 = reinterpret_cast<const float4*>(hf);
    for (int e = beg; e < end; e++) {
        int f = __ldg(csr + e);               // uniform across warp
        unsigned mk = __ldg(msk + f);         // uniform
        if ((mk >> b) & 1u) {
            float4 a = hf4[((size_t)f * B_SZ + b) * 8 + chunk];   // 512B/warp, coalesced
            s0 += fmaxf(a.x + hpa.x, 0.f);
            s1 += fmaxf(a.y + hpa.y, 0.f);
            s2 += fmaxf(a.z + hpb.x, 0.f);
            s3 += fmaxf(a.w + hpb.y, 0.f);
        }
    }

    // msg = s @ W2 : lane computes output dims 2*chunk, 2*chunk+1
    const ULL* sW2p = reinterpret_cast<const ULL*>(sW2);
    ULL acc = 0ull;
    float sv[4] = {s0, s1, s2, s3};
    #pragma unroll
    for (int j = 0; j < 32; j++) {
        float sj = __shfl_sync(0xffffffffu, sv[j & 3], j >> 2, 8);
        acc = f2fma(pk2(sj), sW2p[j*8 + chunk], acc);
    }

    int idx = v * B_SZ + b;
    reinterpret_cast<ULL*>(m)[((size_t)pol * NUM_VN * B_SZ + idx) * 8 + chunk] = acc;
}

// ---------------------------------------------------------------------------
// vn kernel: out = relu([m_x|m_z|h_to] @ We1) @ We2 (per-thread rows)
__global__ void __launch_bounds__(256, 2) vn_kernel(
    const float* __restrict__ m, const float* __restrict__ h_to,
    const float* __restrict__ We1, const float* __restrict__ We2,
    float* __restrict__ out)
{
    __shared__ float4 sW1[384];   // We1 48x32
    __shared__ float4 sW2[128];   // We2 32x16
    int t = threadIdx.x;
    for (int i = t; i < 384; i += 256) sW1[i] = reinterpret_cast<const float4*>(We1)[i];
    if (t < 128) sW2[t] = reinterpret_cast<const float4*>(We2)[t];
    __syncthreads();

    int idx = blockIdx.x * 256 + t;   // idx = v*16 + b
    int v = idx >> 4;
    int b = idx & 15;
    const size_t BVN = (size_t)NUM_VN * B_SZ;

    float feat[48];
    {
        const float4* px = reinterpret_cast<const float4*>(m + (size_t)idx * D_MSG);
        const float4* pz = reinterpret_cast<const float4*>(m + (BVN + idx) * D_MSG);
        const float4* ph = reinterpret_cast<const float4*>(
            h_to + ((size_t)b * NUM_VN + v) * D_EMB);
        #pragma unroll
        for (int q = 0; q < 4; q++) {
            float4 a = px[q];
            feat[4*q+0]=a.x; feat[4*q+1]=a.y; feat[4*q+2]=a.z; feat[4*q+3]=a.w;
        }
        #pragma unroll
        for (int q = 0; q < 4; q++) {
            float4 a = pz[q];
            feat[16+4*q+0]=a.x; feat[16+4*q+1]=a.y; feat[16+4*q+2]=a.z; feat[16+4*q+3]=a.w;
        }
        #pragma unroll
        for (int q = 0; q < 4; q++) {
            float4 a = ph[q];
            feat[32+4*q+0]=a.x; feat[32+4*q+1]=a.y; feat[32+4*q+2]=a.z; feat[32+4*q+3]=a.w;
        }
    }

    ULL acc[16];
    #pragma unroll
    for (int q = 0; q < 16; q++) acc[q] = 0ull;
    #pragma unroll
    for (int d = 0; d < 48; d++) {
        ULL fd = pk2(feat[d]);
        #pragma unroll
        for (int k = 0; k < 8; k++) {
            float4 w = sW1[d*8 + k];
            acc[2*k+0] = f2fma(fd, pkp(w.x, w.y), acc[2*k+0]);
            acc[2*k+1] = f2fma(fd, pkp(w.z, w.w), acc[2*k+1]);
        }
    }

    float hid[32];
    #pragma unroll
    for (int q = 0; q < 16; q++) {
        float2 p = up2(acc[q]);
        hid[2*q+0] = fmaxf(p.x, 0.f);
        hid[2*q+1] = fmaxf(p.y, 0.f);
    }

    ULL o[8];
    #pragma unroll
    for (int q = 0; q < 8; q++) o[q] = 0ull;
    #pragma unroll
    for (int j = 0; j < 32; j++) {
        ULL hj = pk2(hid[j]);
        #pragma unroll
        for (int k = 0; k < 4; k++) {
            float4 w = sW2[j*4 + k];
            o[2*k+0] = f2fma(hj, pkp(w.x, w.y), o[2*k+0]);
            o[2*k+1] = f2fma(hj, pkp(w.z, w.w), o[2*k+1]);
        }
    }

    float4* op = reinterpret_cast<float4*>(out + ((size_t)b * NUM_VN + v) * D_EMB);
    #pragma unroll
    for (int q = 0; q < 4; q++) op[q] = mk4(o[2*q], o[2*q+1]);
}

// ---------------------------------------------------------------------------
extern "C" void kernel_launch(void* const* d_in, const int* in_sizes, int n_in,
                              void* d_out, int out_size) {
    const float* h_from_x   = (const float*)d_in[0];
    const float* h_from_z   = (const float*)d_in[1];
    const float* h_to       = (const float*)d_in[2];
    const int*   syndrome_x = (const int*)d_in[3];
    const int*   syndrome_z = (const int*)d_in[4];
    const int*   from_ind_x = (const int*)d_in[5];
    const int*   to_ind_x   = (const int*)d_in[6];
    const int*   from_ind_z = (const int*)d_in[7];
    const int*   to_ind_z   = (const int*)d_in[8];
    const float* Wx1        = (const float*)d_in[9];
    const float* Wx2        = (const float*)d_in[10];
    const float* Wz1        = (const float*)d_in[11];
    const float* Wz2        = (const float*)d_in[12];
    const float* We1        = (const float*)d_in[13];
    const float* We2        = (const float*)d_in[14];
    float* out = (float*)d_out;

    float *hf_x, *hf_z, *m;
    int *cnt, *incl_x, *incl_z, *bsum_x, *bsum_z, *offs_x, *offs_z, *csr_x, *csr_z;
    unsigned *mask_x, *mask_z;
    cudaGetSymbolAddress((void**)&hf_x, g_hf_x);
    cudaGetSymbolAddress((void**)&hf_z, g_hf_z);
    cudaGetSymbolAddress((void**)&m,    g_m);
    cudaGetSymbolAddress((void**)&cnt,  g_cnt);
    cudaGetSymbolAddress((void**)&incl_x, g_incl_x);
    cudaGetSymbolAddress((void**)&incl_z, g_incl_z);
    cudaGetSymbolAddress((void**)&bsum_x, g_bsum_x);
    cudaGetSymbolAddress((void**)&bsum_z, g_bsum_z);
    cudaGetSymbolAddress((void**)&offs_x, g_offs_x);
    cudaGetSymbolAddress((void**)&offs_z, g_offs_z);
    cudaGetSymbolAddress((void**)&csr_x, g_csr_x);
    cudaGetSymbolAddress((void**)&csr_z, g_csr_z);
    cudaGetSymbolAddress((void**)&mask_x, g_mask_x);
    cudaGetSymbolAddress((void**)&mask_z, g_mask_z);

    int *deg_x = cnt, *deg_z = cnt + NUM_VN;
    int *cur_x = cnt + 2 * NUM_VN, *cur_z = cnt + 3 * NUM_VN;

    cudaMemsetAsync(cnt, 0, 4 * NUM_VN * sizeof(int), 0);

    const int SB = (NUM_VN + 1023) / 1024;   // 49

    prep_kernel<<<(NUM_E + 255) / 256, 256>>>(
        to_ind_x, to_ind_z, syndrome_x, syndrome_z,
        deg_x, deg_z, mask_x, mask_z);

    scan1_kernel<<<dim3(SB, 2), 1024>>>(deg_x, deg_z, incl_x, incl_z, bsum_x, bsum_z);
    scan2_kernel<<<2, 64>>>(bsum_x, bsum_z, SB);
    scan3_kernel<<<dim3(SB, 2), 1024>>>(incl_x, incl_z, bsum_x, bsum_z, offs_x, offs_z);

    fill_kernel<<<(NUM_E + 255) / 256, 256>>>(
        from_ind_x, to_ind_x, from_ind_z, to_ind_z,
        offs_x, offs_z, cur_x, cur_z, csr_x, csr_z);

    // node partials: 100000 warp-units per pol -> 12500 blocks of 8 warps
    np_kernel<<<dim3(12500, 2), 256>>>(h_from_x, h_from_z, Wx1, Wz1, hf_x, hf_z);

    // messages: 200000 warp-units per pol -> 25000 blocks of 8 warps
    msg_kernel<<<dim3(25000, 2), 256>>>(
        h_to, hf_x, hf_z,
        offs_x, csr_x, offs_z, csr_z, mask_x, mask_z,
        Wx1, Wz1, Wx2, Wz2, m);

    vn_kernel<<<(NUM_VN * B_SZ) / 256, 256>>>(m, h_to, We1, We2, out);
}